// round 6
// baseline (speedup 1.0000x reference)
#include <cuda_runtime.h>
#include <cuda_bf16.h>
#include <cstdint>
#include <math.h>

#define BATCH  2
#define SEQ    2048
#define DMODEL 1024
#define NHEAD  16
#define HDIM   64
#define WIN    256
#define MROWS  (BATCH*SEQ)   /* 4096 */

#define KC     3072          /* [hi|hi|lo] x [hi|lo|hi] concatenated K */
#define GN     1024

// ---------------- scratch (allocation-free rule: device globals) ----------------
__device__ float g_q [MROWS*DMODEL];
__device__ float g_k [MROWS*DMODEL];
__device__ float g_v [MROWS*DMODEL];
__device__ float g_ao[MROWS*DMODEL];

__device__ __nv_bfloat16 g_xc [(size_t)MROWS*KC];
__device__ __nv_bfloat16 g_aoc[(size_t)MROWS*KC];
__device__ __nv_bfloat16 g_wqc[(size_t)DMODEL*KC];
__device__ __nv_bfloat16 g_wkc[(size_t)DMODEL*KC];
__device__ __nv_bfloat16 g_wvc[(size_t)DMODEL*KC];
__device__ __nv_bfloat16 g_woc[(size_t)DMODEL*KC];

// head-major bf16 hi|lo splits for attention: [b, h, s, 128] (0..63 hi, 64..127 lo)
__device__ __nv_bfloat16 g_qs[(size_t)MROWS*2*DMODEL];
__device__ __nv_bfloat16 g_ks[(size_t)MROWS*2*DMODEL];
__device__ __nv_bfloat16 g_vs[(size_t)MROWS*2*DMODEL];

// =========================================================================
// common helpers
// =========================================================================
__device__ __forceinline__ uint32_t smem_u32(const void* p) {
    uint32_t a;
    asm("{ .reg .u64 t; cvta.to.shared.u64 t, %1; cvt.u32.u64 %0, t; }"
        : "=r"(a) : "l"(p));
    return a;
}

__device__ __forceinline__ void split4(float4 v, uint2& hi, uint2& lo)
{
    __nv_bfloat162 h01 = __floats2bfloat162_rn(v.x, v.y);
    __nv_bfloat162 h23 = __floats2bfloat162_rn(v.z, v.w);
    __nv_bfloat162 l01 = __floats2bfloat162_rn(v.x - __low2float(h01),
                                               v.y - __high2float(h01));
    __nv_bfloat162 l23 = __floats2bfloat162_rn(v.z - __low2float(h23),
                                               v.w - __high2float(h23));
    hi = make_uint2(*(uint32_t*)&h01, *(uint32_t*)&h23);
    lo = make_uint2(*(uint32_t*)&l01, *(uint32_t*)&l23);
}

#define CP_ASYNC16(dst, src) \
    asm volatile("cp.async.cg.shared.global [%0], [%1], 16;" \
                 :: "r"(dst), "l"(src) : "memory")
#define CP_COMMIT() asm volatile("cp.async.commit_group;" ::: "memory")
#define CP_WAIT1()  asm volatile("cp.async.wait_group 1;"  ::: "memory")
#define CP_WAIT0()  asm volatile("cp.async.wait_group 0;"  ::: "memory")

#define LDMATRIX_X4(r0, r1, r2, r3, addr) \
    asm volatile("ldmatrix.sync.aligned.m8n8.x4.shared.b16 {%0,%1,%2,%3}, [%4];" \
                 : "=r"(r0), "=r"(r1), "=r"(r2), "=r"(r3) : "r"(addr))

#define LDMATRIX_X4_T(r0, r1, r2, r3, addr) \
    asm volatile("ldmatrix.sync.aligned.m8n8.x4.trans.shared.b16 {%0,%1,%2,%3}, [%4];" \
                 : "=r"(r0), "=r"(r1), "=r"(r2), "=r"(r3) : "r"(addr))

#define MMA16816(d, a, b) \
    asm volatile("mma.sync.aligned.m16n8k16.row.col.f32.bf16.bf16.f32 " \
                 "{%0,%1,%2,%3}, {%4,%5,%6,%7}, {%8,%9}, {%0,%1,%2,%3};" \
                 : "+f"((d)[0]), "+f"((d)[1]), "+f"((d)[2]), "+f"((d)[3]) \
                 : "r"((a)[0]), "r"((a)[1]), "r"((a)[2]), "r"((a)[3]), \
                   "r"((b)[0]), "r"((b)[1]))

// =========================================================================
// fp32 [rows x 1024] -> bf16 [rows x 3072] splits (A: hi|hi|lo; B: hi|lo|hi)
// =========================================================================
__global__ __launch_bounds__(256)
void conv_A(const float* __restrict__ in, __nv_bfloat16* __restrict__ out)
{
    size_t idx = (size_t)blockIdx.x * 256 + threadIdx.x;
    int r  = (int)(idx >> 8);
    int c4 = (int)(idx & 255);
    uint2 hi, lo;
    split4(((const float4*)in)[idx], hi, lo);
    __nv_bfloat16* row = out + (size_t)r * KC;
    *(uint2*)(row + c4 * 4)        = hi;
    *(uint2*)(row + 1024 + c4 * 4) = hi;
    *(uint2*)(row + 2048 + c4 * 4) = lo;
}

__global__ __launch_bounds__(256)
void conv_B(const float* __restrict__ in, __nv_bfloat16* __restrict__ out)
{
    size_t idx = (size_t)blockIdx.x * 256 + threadIdx.x;
    int r  = (int)(idx >> 8);
    int c4 = (int)(idx & 255);
    uint2 hi, lo;
    split4(((const float4*)in)[idx], hi, lo);
    __nv_bfloat16* row = out + (size_t)r * KC;
    *(uint2*)(row + c4 * 4)        = hi;
    *(uint2*)(row + 1024 + c4 * 4) = lo;
    *(uint2*)(row + 2048 + c4 * 4) = hi;
}

// =========================================================================
// q,k,v fp32 [4096,1024] -> head-major bf16 hi|lo [b,h,s,128]; Q scaled 1/8
// grid = 4096 rows, 256 threads: thread c4 -> head c4>>4, dim (c4&15)*4
// =========================================================================
__global__ __launch_bounds__(256)
void conv_qkv(const float* __restrict__ q, const float* __restrict__ k,
              const float* __restrict__ v,
              __nv_bfloat16* __restrict__ Qc, __nv_bfloat16* __restrict__ Kc,
              __nv_bfloat16* __restrict__ Vc)
{
    const int r  = blockIdx.x;           // global row = b*SEQ + s
    const int c4 = threadIdx.x;
    const int b  = r >> 11;
    const int s  = r & 2047;
    const int h  = c4 >> 4;
    const int d4 = c4 & 15;
    const size_t src = (size_t)r * DMODEL + c4 * 4;
    const size_t dst = ((size_t)(b * NHEAD + h) * SEQ + s) * 128 + d4 * 4;

    uint2 hi, lo;
    float4 t = *(const float4*)(q + src);
    t.x *= 0.125f; t.y *= 0.125f; t.z *= 0.125f; t.w *= 0.125f;
    split4(t, hi, lo);
    *(uint2*)(Qc + dst)      = hi;
    *(uint2*)(Qc + dst + 64) = lo;

    split4(*(const float4*)(k + src), hi, lo);
    *(uint2*)(Kc + dst)      = hi;
    *(uint2*)(Kc + dst + 64) = lo;

    split4(*(const float4*)(v + src), hi, lo);
    *(uint2*)(Vc + dst)      = hi;
    *(uint2*)(Vc + dst + 64) = lo;
}

// =========================================================================
// C[M,1024] = A[M,3072] * B[1024,3072]^T via mma.sync  (unchanged from R4)
// =========================================================================
#define BKT    32
#define NSTG   3
#define NKT    (KC / BKT)
#define LDK    40
#define TILE_SB (128 * LDK * 2)
#define STAGE_B (2 * TILE_SB)
#define SMEM_GEMM (NSTG * STAGE_B)

__global__ __launch_bounds__(256)
void gemm_mma(const __nv_bfloat16* __restrict__ A,
              const __nv_bfloat16* __restrict__ B,
              float* __restrict__ C)
{
    extern __shared__ __align__(128) char smem[];
    const uint32_t sb = smem_u32(smem);

    const int tid  = threadIdx.x;
    const int lane = tid & 31;
    const int wid  = tid >> 5;
    const int wm   = (wid & 1) * 64;
    const int wn   = (wid >> 1) * 32;

    const __nv_bfloat16* Ag = A + (size_t)(blockIdx.y * 128) * KC;
    const __nv_bfloat16* Bg = B + (size_t)(blockIdx.x * 128) * KC;

    const int cr = tid >> 2;
    const int cc = tid & 3;

    const int arow  = ((lane >> 3) & 1) * 8 + (lane & 7);
    const int ahalf = (lane >> 4) * 8;
    const int brow  = ((lane >> 4) << 3) + (lane & 7);
    const int bhalf = ((lane >> 3) & 1) * 8;

    float acc[4][4][4];
    #pragma unroll
    for (int i = 0; i < 4; i++)
        #pragma unroll
        for (int j = 0; j < 4; j++)
            #pragma unroll
            for (int t = 0; t < 4; t++) acc[i][j][t] = 0.f;

    #pragma unroll
    for (int s = 0; s < NSTG - 1; s++) {
        uint32_t sa = sb + s * STAGE_B;
        #pragma unroll
        for (int i = 0; i < 2; i++) {
            int r = cr + i * 64;
            CP_ASYNC16(sa + (uint32_t)((r * LDK + cc * 8) * 2),
                       Ag + (size_t)r * KC + s * BKT + cc * 8);
            CP_ASYNC16(sa + TILE_SB + (uint32_t)((r * LDK + cc * 8) * 2),
                       Bg + (size_t)r * KC + s * BKT + cc * 8);
        }
        CP_COMMIT();
    }

    for (int kt = 0; kt < NKT; kt++) {
        CP_WAIT1();
        __syncthreads();

        if (kt + NSTG - 1 < NKT) {
            int s  = (kt + NSTG - 1) % NSTG;
            int kn = kt + NSTG - 1;
            uint32_t sa = sb + s * STAGE_B;
            #pragma unroll
            for (int i = 0; i < 2; i++) {
                int r = cr + i * 64;
                CP_ASYNC16(sa + (uint32_t)((r * LDK + cc * 8) * 2),
                           Ag + (size_t)r * KC + kn * BKT + cc * 8);
                CP_ASYNC16(sa + TILE_SB + (uint32_t)((r * LDK + cc * 8) * 2),
                           Bg + (size_t)r * KC + kn * BKT + cc * 8);
            }
        }
        CP_COMMIT();

        const uint32_t sA = sb + (kt % NSTG) * STAGE_B;
        const uint32_t sB = sA + TILE_SB;

        #pragma unroll
        for (int kk = 0; kk < 2; kk++) {
            uint32_t afr[4][4];
            uint32_t bfr[4][2];
            #pragma unroll
            for (int mi = 0; mi < 4; mi++) {
                uint32_t addr = sA + (uint32_t)(((wm + mi * 16 + arow) * LDK
                                               + kk * 16 + ahalf) * 2);
                LDMATRIX_X4(afr[mi][0], afr[mi][1], afr[mi][2], afr[mi][3], addr);
            }
            #pragma unroll
            for (int np = 0; np < 2; np++) {
                uint32_t r0, r1, r2, r3;
                uint32_t addr = sB + (uint32_t)(((wn + np * 16 + brow) * LDK
                                               + kk * 16 + bhalf) * 2);
                LDMATRIX_X4(r0, r1, r2, r3, addr);
                bfr[np * 2][0] = r0;  bfr[np * 2][1] = r1;
                bfr[np * 2 + 1][0] = r2;  bfr[np * 2 + 1][1] = r3;
            }
            #pragma unroll
            for (int mi = 0; mi < 4; mi++)
                #pragma unroll
                for (int ni = 0; ni < 4; ni++)
                    MMA16816(acc[mi][ni], afr[mi], bfr[ni]);
        }
    }

    const int g = lane >> 2;
    const int t = lane & 3;
    float* Cb = C + (size_t)(blockIdx.y * 128 + wm) * GN + blockIdx.x * 128 + wn;
    #pragma unroll
    for (int mi = 0; mi < 4; mi++) {
        #pragma unroll
        for (int ni = 0; ni < 4; ni++) {
            float* p = Cb + (size_t)(mi * 16 + g) * GN + ni * 8 + t * 2;
            *(float2*)p              = make_float2(acc[mi][ni][0], acc[mi][ni][1]);
            *(float2*)(p + 8 * GN)   = make_float2(acc[mi][ni][2], acc[mi][ni][3]);
        }
    }
}

// =========================================================================
// Flash sliding-window attention v2: pre-split bf16 inputs, cp.async
// double-buffered K/V, 8 warps x 16 query rows (BQ=128).
// =========================================================================
#define LDA 136
#define SZ_Q  (128 * LDA * 2)         /* 34816 */
#define SZ_KV (64 * LDA * 2)          /* 17408 */
#define ATTN_SMEM (SZ_Q + 4 * SZ_KV)  /* 104448 */

__global__ __launch_bounds__(256, 1)
void attn_mma2(const __nv_bfloat16* __restrict__ Qc,
               const __nv_bfloat16* __restrict__ Kc,
               const __nv_bfloat16* __restrict__ Vc,
               float* __restrict__ o)
{
    extern __shared__ __align__(128) char smem[];
    const uint32_t sQ  = smem_u32(smem);
    const uint32_t sK0 = sQ + SZ_Q;
    const uint32_t sV0 = sK0 + SZ_KV;
    const uint32_t sK1 = sV0 + SZ_KV;
    const uint32_t sV1 = sK1 + SZ_KV;

    const int b   = blockIdx.z;
    const int h   = blockIdx.y;
    const int q0  = blockIdx.x * 128;
    const int tid = threadIdx.x;
    const int lane = tid & 31;
    const int wid  = tid >> 5;
    const int wm   = wid * 16;

    const __nv_bfloat16* qg = Qc + ((size_t)(b * NHEAD + h) * SEQ + q0) * 128;
    const __nv_bfloat16* kg = Kc + ((size_t)(b * NHEAD + h) * SEQ) * 128;
    const __nv_bfloat16* vg = Vc + ((size_t)(b * NHEAD + h) * SEQ) * 128;

    const int kstart = max(0, q0 - 256);
    const int ntiles = (q0 + 128 - kstart) >> 6;

    // ---- prologue: Q tile + KV tile 0 ----
    #pragma unroll
    for (int i = 0; i < 8; i++) {
        int idx = tid + i * 256;         // 0..2047
        int row = idx >> 4;
        int c   = idx & 15;
        CP_ASYNC16(sQ + (uint32_t)(row * (LDA * 2) + c * 16),
                   qg + (size_t)row * 128 + c * 8);
    }
    #pragma unroll
    for (int i = 0; i < 4; i++) {
        int idx = tid + i * 256;         // 0..1023
        int row = idx >> 4;
        int c   = idx & 15;
        CP_ASYNC16(sK0 + (uint32_t)(row * (LDA * 2) + c * 16),
                   kg + (size_t)(kstart + row) * 128 + c * 8);
        CP_ASYNC16(sV0 + (uint32_t)(row * (LDA * 2) + c * 16),
                   vg + (size_t)(kstart + row) * 128 + c * 8);
    }
    CP_COMMIT();

    const int g  = lane >> 2;
    const int t4 = lane & 3;
    const int arow  = ((lane >> 3) & 1) * 8 + (lane & 7);
    const int ahalf = (lane >> 4) * 8;
    const int brow  = ((lane >> 4) << 3) + (lane & 7);
    const int bhalf = ((lane >> 3) & 1) * 8;
    const int vrow  = (lane & 7) + ((lane >> 3) & 1) * 8;
    const int vcol  = (lane >> 4) * 8;

    float m0 = -1e30f, m1 = -1e30f, l0 = 0.f, l1 = 0.f;
    float of[8][4];
    #pragma unroll
    for (int i = 0; i < 8; i++)
        #pragma unroll
        for (int j = 0; j < 4; j++) of[i][j] = 0.f;

    const int qrow0 = q0 + wm + g;
    const int qrow1 = qrow0 + 8;

    for (int t = 0; t < ntiles; t++) {
        const int kb = kstart + t * 64;
        CP_WAIT0();
        __syncthreads();

        // prefetch next tile into the other buffer (overlaps compute below)
        if (t + 1 < ntiles) {
            const uint32_t dK = ((t + 1) & 1) ? sK1 : sK0;
            const uint32_t dV = ((t + 1) & 1) ? sV1 : sV0;
            const int kn = kb + 64;
            #pragma unroll
            for (int i = 0; i < 4; i++) {
                int idx = tid + i * 256;
                int row = idx >> 4;
                int c   = idx & 15;
                CP_ASYNC16(dK + (uint32_t)(row * (LDA * 2) + c * 16),
                           kg + (size_t)(kn + row) * 128 + c * 8);
                CP_ASYNC16(dV + (uint32_t)(row * (LDA * 2) + c * 16),
                           vg + (size_t)(kn + row) * 128 + c * 8);
            }
            CP_COMMIT();
        }

        const uint32_t sK = (t & 1) ? sK1 : sK0;
        const uint32_t sV = (t & 1) ? sV1 : sV0;

        // ---- S = Q' K'^T : 12 k16 segment steps ----
        float sf[8][4];
        #pragma unroll
        for (int i = 0; i < 8; i++)
            #pragma unroll
            for (int j = 0; j < 4; j++) sf[i][j] = 0.f;

        #pragma unroll
        for (int s = 0; s < 12; s++) {
            int acol = ((s < 8) ? 0 : 64) + (s & 3) * 16;
            int bcol = ((s >= 4 && s < 8) ? 64 : 0) + (s & 3) * 16;
            uint32_t af[4];
            LDMATRIX_X4(af[0], af[1], af[2], af[3],
                        sQ + (uint32_t)(((wm + arow) * LDA + acol + ahalf) * 2));
            #pragma unroll
            for (int np = 0; np < 4; np++) {
                uint32_t r0, r1, r2, r3;
                LDMATRIX_X4(r0, r1, r2, r3,
                            sK + (uint32_t)(((np * 16 + brow) * LDA + bcol + bhalf) * 2));
                uint32_t b01[2] = {r0, r1}, b23[2] = {r2, r3};
                MMA16816(sf[np * 2],     af, b01);
                MMA16816(sf[np * 2 + 1], af, b23);
            }
        }

        // ---- mask + online softmax ----
        float tmax0 = -1e30f, tmax1 = -1e30f;
        #pragma unroll
        for (int nt = 0; nt < 8; nt++) {
            int key0 = kb + nt * 8 + t4 * 2;
            int key1 = key0 + 1;
            if (!(key0 <= qrow0 && key0 >= qrow0 - (WIN - 1))) sf[nt][0] = -1e30f;
            if (!(key1 <= qrow0 && key1 >= qrow0 - (WIN - 1))) sf[nt][1] = -1e30f;
            if (!(key0 <= qrow1 && key0 >= qrow1 - (WIN - 1))) sf[nt][2] = -1e30f;
            if (!(key1 <= qrow1 && key1 >= qrow1 - (WIN - 1))) sf[nt][3] = -1e30f;
            tmax0 = fmaxf(tmax0, fmaxf(sf[nt][0], sf[nt][1]));
            tmax1 = fmaxf(tmax1, fmaxf(sf[nt][2], sf[nt][3]));
        }
        tmax0 = fmaxf(tmax0, __shfl_xor_sync(0xffffffffu, tmax0, 1));
        tmax0 = fmaxf(tmax0, __shfl_xor_sync(0xffffffffu, tmax0, 2));
        tmax1 = fmaxf(tmax1, __shfl_xor_sync(0xffffffffu, tmax1, 1));
        tmax1 = fmaxf(tmax1, __shfl_xor_sync(0xffffffffu, tmax1, 2));

        float mn0 = fmaxf(m0, tmax0);
        float mn1 = fmaxf(m1, tmax1);
        float f0 = __expf(m0 - mn0);
        float f1 = __expf(m1 - mn1);
        l0 *= f0; l1 *= f1;
        #pragma unroll
        for (int nt = 0; nt < 8; nt++) {
            of[nt][0] *= f0; of[nt][1] *= f0;
            of[nt][2] *= f1; of[nt][3] *= f1;
        }

        uint32_t phi[8][2], plo[8][2];
        #pragma unroll
        for (int nt = 0; nt < 8; nt++) {
            float p00 = __expf(sf[nt][0] - mn0);
            float p01 = __expf(sf[nt][1] - mn0);
            float p10 = __expf(sf[nt][2] - mn1);
            float p11 = __expf(sf[nt][3] - mn1);
            l0 += p00 + p01;
            l1 += p10 + p11;
            __nv_bfloat162 h0 = __floats2bfloat162_rn(p00, p01);
            __nv_bfloat162 h1 = __floats2bfloat162_rn(p10, p11);
            __nv_bfloat162 e0 = __floats2bfloat162_rn(p00 - __low2float(h0),
                                                      p01 - __high2float(h0));
            __nv_bfloat162 e1 = __floats2bfloat162_rn(p10 - __low2float(h1),
                                                      p11 - __high2float(h1));
            phi[nt][0] = *(uint32_t*)&h0;  phi[nt][1] = *(uint32_t*)&h1;
            plo[nt][0] = *(uint32_t*)&e0;  plo[nt][1] = *(uint32_t*)&e1;
        }
        m0 = mn0; m1 = mn1;

        // ---- O += P V  (P_hi*V_hi + P_hi*V_lo + P_lo*V_hi) ----
        #pragma unroll
        for (int kj = 0; kj < 4; kj++) {
            uint32_t aPhi[4] = { phi[2*kj][0], phi[2*kj][1],
                                 phi[2*kj+1][0], phi[2*kj+1][1] };
            uint32_t aPlo[4] = { plo[2*kj][0], plo[2*kj][1],
                                 plo[2*kj+1][0], plo[2*kj+1][1] };
            #pragma unroll
            for (int np = 0; np < 4; np++) {
                uint32_t r0, r1, r2, r3;
                LDMATRIX_X4_T(r0, r1, r2, r3,
                    sV + (uint32_t)(((kj * 16 + vrow) * LDA + np * 16 + vcol) * 2));
                {
                    uint32_t b01[2] = {r0, r1}, b23[2] = {r2, r3};
                    MMA16816(of[np * 2],     aPhi, b01);
                    MMA16816(of[np * 2 + 1], aPhi, b23);
                    MMA16816(of[np * 2],     aPlo, b01);
                    MMA16816(of[np * 2 + 1], aPlo, b23);
                }
                LDMATRIX_X4_T(r0, r1, r2, r3,
                    sV + (uint32_t)(((kj * 16 + vrow) * LDA + 64 + np * 16 + vcol) * 2));
                {
                    uint32_t b01[2] = {r0, r1}, b23[2] = {r2, r3};
                    MMA16816(of[np * 2],     aPhi, b01);
                    MMA16816(of[np * 2 + 1], aPhi, b23);
                }
            }
        }
    }

    // ---- finalize ----
    l0 += __shfl_xor_sync(0xffffffffu, l0, 1);
    l0 += __shfl_xor_sync(0xffffffffu, l0, 2);
    l1 += __shfl_xor_sync(0xffffffffu, l1, 1);
    l1 += __shfl_xor_sync(0xffffffffu, l1, 2);
    float inv0 = 1.f / l0;
    float inv1 = 1.f / l1;

    float* ob = o + (size_t)(b * SEQ + q0 + wm) * DMODEL + h * HDIM;
    #pragma unroll
    for (int nt = 0; nt < 8; nt++) {
        int col = nt * 8 + t4 * 2;
        *(float2*)(ob + (size_t)g * DMODEL + col) =
            make_float2(of[nt][0] * inv0, of[nt][1] * inv0);
        *(float2*)(ob + (size_t)(g + 8) * DMODEL + col) =
            make_float2(of[nt][2] * inv1, of[nt][3] * inv1);
    }
}

// ---------------------------------------------------------------------------
extern "C" void kernel_launch(void* const* d_in, const int* in_sizes, int n_in,
                              void* d_out, int out_size)
{
    const float* x  = (const float*)d_in[0];
    const float* Wq = (const float*)d_in[1];
    const float* Wk = (const float*)d_in[2];
    const float* Wv = (const float*)d_in[3];
    const float* Wo = (const float*)d_in[4];
    float* out = (float*)d_out;

    float *qp, *kp, *vp, *aop;
    __nv_bfloat16 *xc, *aoc, *wqc, *wkc, *wvc, *woc, *qs, *ks, *vs;
    cudaGetSymbolAddress((void**)&qp,  g_q);
    cudaGetSymbolAddress((void**)&kp,  g_k);
    cudaGetSymbolAddress((void**)&vp,  g_v);
    cudaGetSymbolAddress((void**)&aop, g_ao);
    cudaGetSymbolAddress((void**)&xc,  g_xc);
    cudaGetSymbolAddress((void**)&aoc, g_aoc);
    cudaGetSymbolAddress((void**)&wqc, g_wqc);
    cudaGetSymbolAddress((void**)&wkc, g_wkc);
    cudaGetSymbolAddress((void**)&wvc, g_wvc);
    cudaGetSymbolAddress((void**)&woc, g_woc);
    cudaGetSymbolAddress((void**)&qs,  g_qs);
    cudaGetSymbolAddress((void**)&ks,  g_ks);
    cudaGetSymbolAddress((void**)&vs,  g_vs);

    cudaFuncSetAttribute(gemm_mma, cudaFuncAttributeMaxDynamicSharedMemorySize,
                         SMEM_GEMM);
    cudaFuncSetAttribute(attn_mma2, cudaFuncAttributeMaxDynamicSharedMemorySize,
                         ATTN_SMEM);

    conv_A<<<MROWS, 256>>>(x,  xc);
    conv_B<<<DMODEL, 256>>>(Wq, wqc);
    conv_B<<<DMODEL, 256>>>(Wk, wkc);
    conv_B<<<DMODEL, 256>>>(Wv, wvc);
    conv_B<<<DMODEL, 256>>>(Wo, woc);

    dim3 gdim(GN / 128, MROWS / 128);
    gemm_mma<<<gdim, 256, SMEM_GEMM>>>(xc, wqc, qp);
    gemm_mma<<<gdim, 256, SMEM_GEMM>>>(xc, wkc, kp);
    gemm_mma<<<gdim, 256, SMEM_GEMM>>>(xc, wvc, vp);

    conv_qkv<<<MROWS, 256>>>(qp, kp, vp, qs, ks, vs);

    attn_mma2<<<dim3(SEQ / 128, NHEAD, BATCH), 256, ATTN_SMEM>>>(qs, ks, vs, aop);

    conv_A<<<MROWS, 256>>>(aop, aoc);
    gemm_mma<<<gdim, 256, SMEM_GEMM>>>(aoc, woc, out);
}